// round 8
// baseline (speedup 1.0000x reference)
#include <cuda_runtime.h>
#include <cuda_bf16.h>
#include <cstdint>

#define CIN 256
#define COUT 256
#define NB 32
#define ZSZ (NB * COUT * 36)
#define XSZ (NB * COUT * 900)
#define OSZ (NB * COUT * 625)

// Winograd tile counts: x: 15x15*32 = 7200 (pad 7296 = 228*32), z: 9*32 = 288 (pad 384)
#define NTX 7296
#define NTZ 384
#define VSX ((size_t)NTX * 512)
#define VSZ ((size_t)NTZ * 512)

__device__ __align__(16) __nv_bfloat16 g_wU[4][16 * 256 * 512]; // [path][(pos*256+oc)*512 + comp*256+cin]
__device__ float g_bias[4][COUT];
__device__ __align__(16) __nv_bfloat16 g_V[16 * NTX * 512];     // [pos][tile][comp*256+cin]
__device__ __align__(16) __nv_bfloat16 g_Vz[16 * NTZ * 512];
__device__ float g_zf[2][ZSZ];
__device__ float g_xf[2][XSZ];

struct PrepArgs {
    const float* w[4];
    const float* g[4];
    const float* b[4];
    const float* m[4];
    const float* v[4];
};

// ============================ helpers ========================================
__device__ __forceinline__ uint32_t smem_u32(const void* p) {
    uint32_t a;
    asm("{ .reg .u64 t; cvta.to.shared.u64 t, %1; cvt.u32.u64 %0, t; }"
        : "=r"(a) : "l"(p));
    return a;
}
__device__ __forceinline__ void cp16(uint32_t dst, const void* src) {
    asm volatile("cp.async.cg.shared.global [%0], [%1], 16;" :: "r"(dst), "l"(src));
}
__device__ __forceinline__ void cp_commit() {
    asm volatile("cp.async.commit_group;" ::: "memory");
}
template <int N>
__device__ __forceinline__ void cp_wait() {
    asm volatile("cp.async.wait_group %0;" :: "n"(N) : "memory");
}

#define LDSM4(r, addr)                                                         \
    asm volatile("ldmatrix.sync.aligned.m8n8.x4.shared.b16 {%0,%1,%2,%3},[%4];"\
        : "=r"((r)[0]), "=r"((r)[1]), "=r"((r)[2]), "=r"((r)[3]) : "r"(addr))

#define MMA(d, a, b0, b1)                                                      \
    asm volatile("mma.sync.aligned.m16n8k16.row.col.f32.bf16.bf16.f32 "        \
        "{%0,%1,%2,%3}, {%4,%5,%6,%7}, {%8,%9}, {%0,%1,%2,%3};"                \
        : "+f"((d)[0]), "+f"((d)[1]), "+f"((d)[2]), "+f"((d)[3])               \
        : "r"((a)[0]), "r"((a)[1]), "r"((a)[2]), "r"((a)[3]),                  \
          "r"(b0), "r"(b1))

__device__ __forceinline__ void bsplit(float v, __nv_bfloat16& hi, __nv_bfloat16& lo) {
    hi = __float2bfloat16(v);
    lo = __float2bfloat16(v - __bfloat162float(hi));
}

// ============================ prep: weight transform =========================
__global__ void prep_kernel(PrepArgs a) {
    int i = blockIdx.x * blockDim.x + threadIdx.x;       // 262144 items
    int path = i >> 16;
    int oc   = (i >> 8) & 255;
    int cin  = i & 255;
    float inv = a.g[path][oc] * rsqrtf(a.v[path][oc] + 1e-5f);
    const float* wp = a.w[path] + oc * 2304 + cin * 9;
    float w[3][3];
#pragma unroll
    for (int r = 0; r < 3; r++)
#pragma unroll
        for (int c = 0; c < 3; c++) w[r][c] = wp[r * 3 + c] * inv;

    float T[4][3];
#pragma unroll
    for (int j = 0; j < 3; j++) {
        T[0][j] = w[0][j];
        T[1][j] = 0.5f * (w[0][j] + w[1][j] + w[2][j]);
        T[2][j] = 0.5f * (w[0][j] - w[1][j] + w[2][j]);
        T[3][j] = w[2][j];
    }
#pragma unroll
    for (int r = 0; r < 4; r++) {
        float U[4];
        U[0] = T[r][0];
        U[1] = 0.5f * (T[r][0] + T[r][1] + T[r][2]);
        U[2] = 0.5f * (T[r][0] - T[r][1] + T[r][2]);
        U[3] = T[r][2];
#pragma unroll
        for (int c = 0; c < 4; c++) {
            __nv_bfloat16 hi, lo;
            bsplit(U[c], hi, lo);
            size_t base = ((size_t)((r * 4 + c) * 256 + oc)) * 512 + cin;
            g_wU[path][base]       = hi;
            g_wU[path][base + 256] = lo;
        }
    }
    if (i < 1024) {
        int p2 = i >> 8, oc2 = i & 255;
        float inv2 = a.g[p2][oc2] * rsqrtf(a.v[p2][oc2] + 1e-5f);
        g_bias[p2][oc2] = a.b[p2][oc2] - a.m[p2][oc2] * inv2;
    }
}

// ============================ input transforms ===============================
__device__ __forceinline__ void wino_fwd(const float d[4][4], float V[4][4]) {
    float t[4][4];
#pragma unroll
    for (int j = 0; j < 4; j++) {
        t[0][j] = d[0][j] - d[2][j];
        t[1][j] = d[1][j] + d[2][j];
        t[2][j] = d[2][j] - d[1][j];
        t[3][j] = d[1][j] - d[3][j];
    }
#pragma unroll
    for (int i = 0; i < 4; i++) {
        V[i][0] = t[i][0] - t[i][2];
        V[i][1] = t[i][1] + t[i][2];
        V[i][2] = t[i][2] - t[i][1];
        V[i][3] = t[i][1] - t[i][3];
    }
}

__global__ __launch_bounds__(256)
void xform_x(const float* __restrict__ x) {
    __shared__ float sd[8][1024];
    __shared__ __align__(16) __nv_bfloat16 sV[16][16][2][8];
    const int img = blockIdx.x, cg = blockIdx.y, tid = threadIdx.x;
    const float* src = x + ((size_t)img * 256 + cg * 8) * 1024;
#pragma unroll
    for (int k = 0; k < 32; k++) {
        int lin = k * 256 + tid;
        sd[lin >> 10][lin & 1023] = src[lin];
    }
    __syncthreads();

    for (int cc = 0; cc < 15; cc++) {
        const int tl = tid >> 3, c = tid & 7;
        const int tile = cc * 16 + tl;
        if (tid < 128 && tile < 225) {
            int ty = tile / 15, tx = tile - ty * 15;
            float d[4][4], V[4][4];
#pragma unroll
            for (int i = 0; i < 4; i++)
#pragma unroll
                for (int j = 0; j < 4; j++)
                    d[i][j] = sd[c][(2 * ty + i) * 32 + 2 * tx + j];
            wino_fwd(d, V);
#pragma unroll
            for (int i = 0; i < 4; i++)
#pragma unroll
                for (int j = 0; j < 4; j++) {
                    __nv_bfloat16 hi, lo;
                    bsplit(V[i][j], hi, lo);
                    sV[tl][i * 4 + j][0][c] = hi;
                    sV[tl][i * 4 + j][1][c] = lo;
                }
        }
        __syncthreads();
#pragma unroll
        for (int k = 0; k < 2; k++) {
            int cid = k * 256 + tid;                 // 512 chunks
            int tl2 = cid >> 5, pos = (cid >> 1) & 15, comp = cid & 1;
            int tile2 = cc * 16 + tl2;
            if (tile2 < 225) {
                uint4 val = *(const uint4*)&sV[tl2][pos][comp][0];
                *(uint4*)(g_V + (size_t)pos * VSX +
                          ((size_t)img * 225 + tile2) * 512 + comp * 256 + cg * 8) = val;
            }
        }
        __syncthreads();
    }
}

__global__ __launch_bounds__(128)
void xform_z(const float* __restrict__ z) {
    __shared__ float sd[8][64];
    __shared__ __align__(16) __nv_bfloat16 sVz[9][16][2][8];
    const int img = blockIdx.x, cg = blockIdx.y, tid = threadIdx.x;
    const float* src = z + ((size_t)img * 256 + cg * 8) * 64;
#pragma unroll
    for (int k = 0; k < 4; k++) {
        int lin = k * 128 + tid;
        sd[lin >> 6][lin & 63] = src[lin];
    }
    __syncthreads();
    if (tid < 72) {
        int tl = tid >> 3, c = tid & 7;
        int ty = tl / 3, tx = tl - ty * 3;
        float d[4][4], V[4][4];
#pragma unroll
        for (int i = 0; i < 4; i++)
#pragma unroll
            for (int j = 0; j < 4; j++)
                d[i][j] = sd[c][(2 * ty + i) * 8 + 2 * tx + j];
        wino_fwd(d, V);
#pragma unroll
        for (int i = 0; i < 4; i++)
#pragma unroll
            for (int j = 0; j < 4; j++) {
                __nv_bfloat16 hi, lo;
                bsplit(V[i][j], hi, lo);
                sVz[tl][i * 4 + j][0][c] = hi;
                sVz[tl][i * 4 + j][1][c] = lo;
            }
    }
    __syncthreads();
#pragma unroll
    for (int k = 0; k < 3; k++) {
        int cid = k * 128 + tid;                     // 288 chunks
        if (cid < 288) {
            int tl = cid >> 5, pos = (cid >> 1) & 15, comp = cid & 1;
            uint4 val = *(const uint4*)&sVz[tl][pos][comp][0];
            *(uint4*)(g_Vz + (size_t)pos * VSZ +
                      ((size_t)img * 9 + tl) * 512 + comp * 256 + cg * 8) = val;
        }
    }
}

// ================== fused GEMM + inverse transform ===========================
// Block: 32 tiles x 128 oc. Loops 16 positions; per position a K=256 GEMM
// (3-term bf16 split), then folds acc into 4 output-pixel accumulators with
// exact F(2,3) inverse coefficients. Writes xf/zf directly.
// blocks 0..911: x (q=branch*2+o, bt=0..227); 912..959: z (bt=0..11)
#define ASTR 144u
#define ABUFW (32u * ASTR)        // 4608
#define BSTR 144u
#define BBUFW (128u * BSTR)       // 18432
#define SM_AOFF (2u * BBUFW)      // 36864
#define GEMM_SMEM 68096u          // epilogue: 128*132*4 + 512

__global__ __launch_bounds__(128, 2)
void wino_gemm_fused() {
    extern __shared__ __align__(16) char smem[];
    const int tid = threadIdx.x, lid = tid & 31, wid = tid >> 5;
    const int warp_n = wid;                     // 4 warps split N=128 into 32 each
    const uint32_t sBu = smem_u32(smem);

    const int bid = blockIdx.x;
    const bool zmode = (bid >= 912);
    int branch, o, tile0;
    if (zmode) {
        int zb = bid - 912;
        int q = zb / 12; tile0 = (zb - q * 12) * 32;
        branch = q >> 1; o = q & 1;
    } else {
        int q = bid / 228; tile0 = (bid - q * 228) * 32;
        branch = q >> 1; o = q & 1;
    }
    const int path = zmode ? 2 * branch : 1 + 2 * branch;
    const int ocb = o * 128;
    const __nv_bfloat16* vbase = zmode ? g_Vz : g_V;
    const size_t VS = zmode ? VSZ : VSX;
    const __nv_bfloat16* wbase = g_wU[path];

    // bias -> smem (region beyond GEMM buffers, no alias)
    float* sBias = (float*)(smem + 128 * 132 * 4);
    if (tid < 128) sBias[tid] = g_bias[path][ocb + tid];

    auto copyAB = [&](int g) {
        const int pos = g >> 3, ch = g & 7, buf = g & 1;
        const int c0 = ch * 32;
        const __nv_bfloat16* va = vbase + (size_t)pos * VS + (size_t)tile0 * 512;
        const __nv_bfloat16* wa = wbase + (size_t)(pos * 256 + ocb) * 512;
#pragma unroll
        for (int k = 0; k < 2; k++) {            // A: 256 cp16
            int id = tid + k * 128;
            int row = id >> 3, part = id & 7, comp = part >> 2, kq = part & 3;
            cp16(sBu + SM_AOFF + buf * ABUFW + row * ASTR + comp * 64 + kq * 16,
                 va + (size_t)row * 512 + comp * 256 + c0 + kq * 8);
        }
#pragma unroll
        for (int k = 0; k < 8; k++) {            // B: 1024 cp16
            int id = tid + k * 128;
            int row = id >> 3, part = id & 7, comp = part >> 2, kq = part & 3;
            cp16(sBu + buf * BBUFW + row * BSTR + comp * 64 + kq * 16,
                 wa + (size_t)row * 512 + comp * 256 + c0 + kq * 8);
        }
        cp_commit();
    };

    // fragment base addresses (per buffer parity)
    uint32_t aBase[2], bBase[2][2];
    {
        int am = (lid & 7) + ((lid >> 3) & 1) * 8;
        uint32_t acol = (lid >> 4) << 4;
#pragma unroll
        for (int buf = 0; buf < 2; buf++)
            aBase[buf] = sBu + SM_AOFF + buf * ABUFW + am * ASTR + acol;
        uint32_t bcol = ((lid >> 3) & 1) << 4;
#pragma unroll
        for (int buf = 0; buf < 2; buf++)
#pragma unroll
            for (int j = 0; j < 2; j++) {
                int n = warp_n * 32 + j * 16 + (lid & 7) + (lid >> 4) * 8;
                bBase[buf][j] = sBu + buf * BBUFW + n * BSTR + bcol;
            }
    }

    float O[4][2][4][4];
#pragma unroll
    for (int px = 0; px < 4; px++)
#pragma unroll
        for (int t = 0; t < 2; t++)
#pragma unroll
            for (int j = 0; j < 4; j++)
#pragma unroll
                for (int e = 0; e < 4; e++) O[px][t][j][e] = 0.f;

    copyAB(0);

#pragma unroll 1
    for (int p = 0; p < 16; p++) {
        float acc[2][4][4];
#pragma unroll
        for (int t = 0; t < 2; t++)
#pragma unroll
            for (int j = 0; j < 4; j++)
#pragma unroll
                for (int e = 0; e < 4; e++) acc[t][j][e] = 0.f;

#pragma unroll
        for (int ch = 0; ch < 8; ch++) {
            const int g = p * 8 + ch, buf = g & 1;
            __syncthreads();
            if (g + 1 < 128) { copyAB(g + 1); cp_wait<1>(); }
            else             { cp_wait<0>(); }
            __syncthreads();

#pragma unroll
            for (int ks = 0; ks < 2; ks++) {
                uint32_t ah[2][4], al[2][4], bq[2][4];
#pragma unroll
                for (int t = 0; t < 2; t++)
                    LDSM4(ah[t], aBase[buf] + t * (16 * ASTR) + ks * 32);
#pragma unroll
                for (int t = 0; t < 2; t++)
                    LDSM4(al[t], aBase[buf] + t * (16 * ASTR) + ks * 32 + 64);
#pragma unroll
                for (int j = 0; j < 2; j++)
                    LDSM4(bq[j], bBase[buf][j] + ks * 32);
                // hi*hi
#pragma unroll
                for (int t = 0; t < 2; t++)
#pragma unroll
                    for (int j = 0; j < 2; j++) {
                        MMA(acc[t][2 * j],     ah[t], bq[j][0], bq[j][1]);
                        MMA(acc[t][2 * j + 1], ah[t], bq[j][2], bq[j][3]);
                    }
                // lo*hi
#pragma unroll
                for (int t = 0; t < 2; t++)
#pragma unroll
                    for (int j = 0; j < 2; j++) {
                        MMA(acc[t][2 * j],     al[t], bq[j][0], bq[j][1]);
                        MMA(acc[t][2 * j + 1], al[t], bq[j][2], bq[j][3]);
                    }
                // hi*lo
#pragma unroll
                for (int j = 0; j < 2; j++)
                    LDSM4(bq[j], bBase[buf][j] + ks * 32 + 64);
#pragma unroll
                for (int t = 0; t < 2; t++)
#pragma unroll
                    for (int j = 0; j < 2; j++) {
                        MMA(acc[t][2 * j],     ah[t], bq[j][0], bq[j][1]);
                        MMA(acc[t][2 * j + 1], ah[t], bq[j][2], bq[j][3]);
                    }
            }
        }

        // fold into output-pixel accumulators: coeffs from A^T = [[1,1,1,0],[0,1,-1,-1]]
        const int pr = p >> 2, pc = p & 3;
        const float cr0 = (pr < 3) ? 1.f : 0.f;
        const float cr1 = (pr == 0) ? 0.f : ((pr == 1) ? 1.f : -1.f);
        const float cc0 = (pc < 3) ? 1.f : 0.f;
        const float cc1 = (pc == 0) ? 0.f : ((pc == 1) ? 1.f : -1.f);
        const float k00 = cr0 * cc0, k01 = cr0 * cc1, k10 = cr1 * cc0, k11 = cr1 * cc1;
#pragma unroll
        for (int t = 0; t < 2; t++)
#pragma unroll
            for (int j = 0; j < 4; j++)
#pragma unroll
                for (int e = 0; e < 4; e++) {
                    float a = acc[t][j][e];
                    O[0][t][j][e] = fmaf(k00, a, O[0][t][j][e]);
                    O[1][t][j][e] = fmaf(k01, a, O[1][t][j][e]);
                    O[2][t][j][e] = fmaf(k10, a, O[2][t][j][e]);
                    O[3][t][j][e] = fmaf(k11, a, O[3][t][j][e]);
                }
    }
    __syncthreads();

    // ---- epilogue: O -> smem [oc][tile*4+px] -> direct xf/zf ----------------
    float* sOut = (float*)smem;
#pragma unroll
    for (int px = 0; px < 4; px++)
#pragma unroll
        for (int t = 0; t < 2; t++)
#pragma unroll
            for (int j = 0; j < 4; j++) {
                int r = t * 16 + (lid >> 2);
                int c = warp_n * 32 + (j >> 1) * 16 + (j & 1) * 8 + (lid & 3) * 2;
                sOut[c * 132 + r * 4 + px]             = O[px][t][j][0];
                sOut[(c + 1) * 132 + r * 4 + px]       = O[px][t][j][1];
                sOut[c * 132 + (r + 8) * 4 + px]       = O[px][t][j][2];
                sOut[(c + 1) * 132 + (r + 8) * 4 + px] = O[px][t][j][3];
            }
    __syncthreads();

    {
        const int tile = tid >> 2, px = tid & 3;
        const int i = px >> 1, jx = px & 1;
        const int gt = tile0 + tile;
        bool valid;
        float* base;
        size_t stride;
        if (zmode) {
            valid = gt < 288;
            int img = gt / 9, lt = gt - img * 9;
            int ty = lt / 3, tx = lt - ty * 3;
            base = g_zf[branch] + ((size_t)img * COUT + ocb) * 36 +
                   (2 * ty + i) * 6 + 2 * tx + jx;
            stride = 36;
        } else {
            valid = gt < 7200;
            int img = gt / 225, lt = gt - img * 225;
            int ty = lt / 15, tx = lt - ty * 15;
            base = g_xf[branch] + ((size_t)img * COUT + ocb) * 900 +
                   (2 * ty + i) * 30 + 2 * tx + jx;
            stride = 900;
        }
        if (valid) {
#pragma unroll 8
            for (int k = 0; k < 128; k++)
                base[(size_t)k * stride] = sOut[k * 132 + tid] + sBias[k];
        }
    }
}

// ============================ depthwise xcorr ================================
__global__ __launch_bounds__(640)
void xcorr_kernel(float* __restrict__ out) {
    __shared__ float s_x[900];
    __shared__ float s_z[36];
    const int branch = blockIdx.y;
    const int bc = blockIdx.x;
    const int tid = threadIdx.x;
    if (tid < 36) s_z[tid] = g_zf[branch][(size_t)bc * 36 + tid];
    for (int i = tid; i < 900; i += 640) s_x[i] = g_xf[branch][(size_t)bc * 900 + i];
    __syncthreads();
    if (tid < 625) {
        int oy = tid / 25, ox = tid % 25;
        float s = 0.f;
#pragma unroll
        for (int u = 0; u < 6; u++)
#pragma unroll
            for (int v = 0; v < 6; v++)
                s = fmaf(s_z[u * 6 + v], s_x[(oy + u) * 30 + ox + v], s);
        out[(size_t)branch * OSZ + (size_t)bc * 625 + tid] = s;
    }
}

// ============================ launch =========================================
extern "C" void kernel_launch(void* const* d_in, const int* in_sizes, int n_in,
                              void* d_out, int out_size) {
    const float* z = (const float*)d_in[0];
    const float* x = (const float*)d_in[1];

    PrepArgs pa;
    for (int p = 0; p < 4; p++) {
        pa.w[p] = (const float*)d_in[2 + p * 5 + 0];
        pa.g[p] = (const float*)d_in[2 + p * 5 + 1];
        pa.b[p] = (const float*)d_in[2 + p * 5 + 2];
        pa.m[p] = (const float*)d_in[2 + p * 5 + 3];
        pa.v[p] = (const float*)d_in[2 + p * 5 + 4];
    }

    cudaFuncSetAttribute(wino_gemm_fused,
                         cudaFuncAttributeMaxDynamicSharedMemorySize, GEMM_SMEM);
    cudaFuncSetAttribute(wino_gemm_fused,
                         cudaFuncAttributePreferredSharedMemoryCarveout, 100);

    prep_kernel<<<1024, 256>>>(pa);
    xform_x<<<dim3(32, 32), 256>>>(x);
    xform_z<<<dim3(32, 32), 128>>>(z);
    wino_gemm_fused<<<960, 128, GEMM_SMEM>>>();
    xcorr_kernel<<<dim3(NB * COUT, 2), 640>>>((float*)d_out);
}

// round 9
// speedup vs baseline: 1.3715x; 1.3715x over previous
#include <cuda_runtime.h>
#include <cuda_fp16.h>
#include <cstdint>

#define CIN 256
#define COUT 256
#define NB 32
#define ZSZ (NB * COUT * 36)
#define XSZ (NB * COUT * 900)
#define OSZ (NB * COUT * 625)

// Winograd tile counts: x: 15x15*32 = 7200 (pad 7296 = 228*32), z: 288 (pad 384)
#define NTX 7296
#define NTZ 384
#define VSX ((size_t)NTX * 512)
#define VSZ ((size_t)NTZ * 512)

__device__ __align__(16) __half g_wU[4][16 * 256 * 256]; // [path][(pos*256+oc)*256 + cin]  single fp16
__device__ float g_bias[4][COUT];
__device__ __align__(16) __half g_V[16 * NTX * 512];     // [pos][tile][comp*256+cin]  hi/lo fp16
__device__ __align__(16) __half g_Vz[16 * NTZ * 512];
__device__ float g_M[2][(size_t)NTX * 16 * 256];         // [branch][tile][pos][oc]
__device__ float g_Mz[2][(size_t)NTZ * 16 * 256];
__device__ float g_zf[2][ZSZ];
__device__ float g_xf[2][XSZ];

struct PrepArgs {
    const float* w[4];
    const float* g[4];
    const float* b[4];
    const float* m[4];
    const float* v[4];
};

// ============================ helpers ========================================
__device__ __forceinline__ uint32_t smem_u32(const void* p) {
    uint32_t a;
    asm("{ .reg .u64 t; cvta.to.shared.u64 t, %1; cvt.u32.u64 %0, t; }"
        : "=r"(a) : "l"(p));
    return a;
}
__device__ __forceinline__ void cp16(uint32_t dst, const void* src) {
    asm volatile("cp.async.cg.shared.global [%0], [%1], 16;" :: "r"(dst), "l"(src));
}
__device__ __forceinline__ void cp_commit() {
    asm volatile("cp.async.commit_group;" ::: "memory");
}
template <int N>
__device__ __forceinline__ void cp_wait() {
    asm volatile("cp.async.wait_group %0;" :: "n"(N) : "memory");
}

#define LDSM4(r, addr)                                                         \
    asm volatile("ldmatrix.sync.aligned.m8n8.x4.shared.b16 {%0,%1,%2,%3},[%4];"\
        : "=r"((r)[0]), "=r"((r)[1]), "=r"((r)[2]), "=r"((r)[3]) : "r"(addr))

#define MMA(d, a, b0, b1)                                                      \
    asm volatile("mma.sync.aligned.m16n8k16.row.col.f32.f16.f16.f32 "          \
        "{%0,%1,%2,%3}, {%4,%5,%6,%7}, {%8,%9}, {%0,%1,%2,%3};"                \
        : "+f"((d)[0]), "+f"((d)[1]), "+f"((d)[2]), "+f"((d)[3])               \
        : "r"((a)[0]), "r"((a)[1]), "r"((a)[2]), "r"((a)[3]),                  \
          "r"(b0), "r"(b1))

__device__ __forceinline__ void hsplit(float v, __half& hi, __half& lo) {
    hi = __float2half_rn(v);
    lo = __float2half_rn(v - __half2float(hi));
}

// ============================ prep: weight transform =========================
__global__ void prep_kernel(PrepArgs a) {
    int i = blockIdx.x * blockDim.x + threadIdx.x;       // 262144 items
    int path = i >> 16;
    int oc   = (i >> 8) & 255;
    int cin  = i & 255;
    float inv = a.g[path][oc] * rsqrtf(a.v[path][oc] + 1e-5f);
    const float* wp = a.w[path] + oc * 2304 + cin * 9;
    float w[3][3];
#pragma unroll
    for (int r = 0; r < 3; r++)
#pragma unroll
        for (int c = 0; c < 3; c++) w[r][c] = wp[r * 3 + c] * inv;

    float T[4][3];
#pragma unroll
    for (int j = 0; j < 3; j++) {
        T[0][j] = w[0][j];
        T[1][j] = 0.5f * (w[0][j] + w[1][j] + w[2][j]);
        T[2][j] = 0.5f * (w[0][j] - w[1][j] + w[2][j]);
        T[3][j] = w[2][j];
    }
#pragma unroll
    for (int r = 0; r < 4; r++) {
        float U[4];
        U[0] = T[r][0];
        U[1] = 0.5f * (T[r][0] + T[r][1] + T[r][2]);
        U[2] = 0.5f * (T[r][0] - T[r][1] + T[r][2]);
        U[3] = T[r][2];
#pragma unroll
        for (int c = 0; c < 4; c++)
            g_wU[path][((size_t)((r * 4 + c) * 256 + oc)) * 256 + cin] =
                __float2half_rn(U[c]);
    }
    if (i < 1024) {
        int p2 = i >> 8, oc2 = i & 255;
        float inv2 = a.g[p2][oc2] * rsqrtf(a.v[p2][oc2] + 1e-5f);
        g_bias[p2][oc2] = a.b[p2][oc2] - a.m[p2][oc2] * inv2;
    }
}

// ============================ input transforms ===============================
__device__ __forceinline__ void wino_fwd(const float d[4][4], float V[4][4]) {
    float t[4][4];
#pragma unroll
    for (int j = 0; j < 4; j++) {
        t[0][j] = d[0][j] - d[2][j];
        t[1][j] = d[1][j] + d[2][j];
        t[2][j] = d[2][j] - d[1][j];
        t[3][j] = d[1][j] - d[3][j];
    }
#pragma unroll
    for (int i = 0; i < 4; i++) {
        V[i][0] = t[i][0] - t[i][2];
        V[i][1] = t[i][1] + t[i][2];
        V[i][2] = t[i][2] - t[i][1];
        V[i][3] = t[i][1] - t[i][3];
    }
}

__global__ __launch_bounds__(256)
void xform_x(const float* __restrict__ x) {
    __shared__ float sd[8][1024];
    __shared__ __align__(16) __half sV[16][16][2][8];
    const int img = blockIdx.x, cg = blockIdx.y, tid = threadIdx.x;
    const float* src = x + ((size_t)img * 256 + cg * 8) * 1024;
#pragma unroll
    for (int k = 0; k < 32; k++) {
        int lin = k * 256 + tid;
        sd[lin >> 10][lin & 1023] = src[lin];
    }
    __syncthreads();

    for (int cc = 0; cc < 15; cc++) {
        const int tl = tid >> 3, c = tid & 7;
        const int tile = cc * 16 + tl;
        if (tid < 128 && tile < 225) {
            int ty = tile / 15, tx = tile - ty * 15;
            float d[4][4], V[4][4];
#pragma unroll
            for (int i = 0; i < 4; i++)
#pragma unroll
                for (int j = 0; j < 4; j++)
                    d[i][j] = sd[c][(2 * ty + i) * 32 + 2 * tx + j];
            wino_fwd(d, V);
#pragma unroll
            for (int i = 0; i < 4; i++)
#pragma unroll
                for (int j = 0; j < 4; j++) {
                    __half hi, lo;
                    hsplit(V[i][j], hi, lo);
                    sV[tl][i * 4 + j][0][c] = hi;
                    sV[tl][i * 4 + j][1][c] = lo;
                }
        }
        __syncthreads();
#pragma unroll
        for (int k = 0; k < 2; k++) {
            int cid = k * 256 + tid;                 // 512 chunks
            int tl2 = cid >> 5, pos = (cid >> 1) & 15, comp = cid & 1;
            int tile2 = cc * 16 + tl2;
            if (tile2 < 225) {
                uint4 val = *(const uint4*)&sV[tl2][pos][comp][0];
                *(uint4*)(g_V + (size_t)pos * VSX +
                          ((size_t)img * 225 + tile2) * 512 + comp * 256 + cg * 8) = val;
            }
        }
        __syncthreads();
    }
}

__global__ __launch_bounds__(128)
void xform_z(const float* __restrict__ z) {
    __shared__ float sd[8][64];
    __shared__ __align__(16) __half sVz[9][16][2][8];
    const int img = blockIdx.x, cg = blockIdx.y, tid = threadIdx.x;
    const float* src = z + ((size_t)img * 256 + cg * 8) * 64;
#pragma unroll
    for (int k = 0; k < 4; k++) {
        int lin = k * 128 + tid;
        sd[lin >> 6][lin & 63] = src[lin];
    }
    __syncthreads();
    if (tid < 72) {
        int tl = tid >> 3, c = tid & 7;
        int ty = tl / 3, tx = tl - ty * 3;
        float d[4][4], V[4][4];
#pragma unroll
        for (int i = 0; i < 4; i++)
#pragma unroll
            for (int j = 0; j < 4; j++)
                d[i][j] = sd[c][(2 * ty + i) * 8 + 2 * tx + j];
        wino_fwd(d, V);
#pragma unroll
        for (int i = 0; i < 4; i++)
#pragma unroll
            for (int j = 0; j < 4; j++) {
                __half hi, lo;
                hsplit(V[i][j], hi, lo);
                sVz[tl][i * 4 + j][0][c] = hi;
                sVz[tl][i * 4 + j][1][c] = lo;
            }
    }
    __syncthreads();
#pragma unroll
    for (int k = 0; k < 3; k++) {
        int cid = k * 128 + tid;                     // 288 chunks
        if (cid < 288) {
            int tl = cid >> 5, pos = (cid >> 1) & 15, comp = cid & 1;
            uint4 val = *(const uint4*)&sVz[tl][pos][comp][0];
            *(uint4*)(g_Vz + (size_t)pos * VSZ +
                      ((size_t)img * 9 + tl) * 512 + comp * 256 + cg * 8) = val;
        }
    }
}

// ============================ batched GEMM ===================================
// Per block: D[128 tile, 128 oc] = V[128,256] * U[128,256]^T
// 2-term fp16 split: A = hi+lo, B = single fp16. M layout [tile][pos][oc].
// blocks 0..3647: x (b,o,p,mt=57); 3648..3839: z (b,o,p,mt=3)
#define ASTR 144u
#define ABUF (128u * ASTR)        // 18432
#define BSTR 80u
#define BBUF (128u * BSTR)        // 10240
#define BOFF (2u * ABUF)          // 36864
#define GEMM_SMEM (BOFF + 2u * BBUF)   // 57344

__global__ __launch_bounds__(128, 2)
void wino_gemm() {
    extern __shared__ __align__(16) char smem[];
    const int tid = threadIdx.x, lid = tid & 31, wid = tid >> 5;
    const int warp_m = wid >> 1, warp_n = wid & 1;
    const uint32_t sBu = smem_u32(smem);

    const int bid = blockIdx.x;
    const __half *vsrc, *wsrc;
    float* mdst;
    if (bid < 3648) {
        int q = bid / 57, mt = bid - q * 57;
        int p = q & 15; q >>= 4;
        int o = q & 1, b = q >> 1;
        vsrc = g_V + (size_t)p * VSX + (size_t)mt * 128 * 512;
        wsrc = g_wU[1 + 2 * b] + ((size_t)(p * 256) + o * 128) * 256;
        mdst = g_M[b] + ((size_t)mt * 128) * 4096 + p * 256 + o * 128;
    } else {
        int zb = bid - 3648;
        int q = zb / 3, mt = zb - q * 3;
        int p = q & 15; q >>= 4;
        int o = q & 1, b = q >> 1;
        vsrc = g_Vz + (size_t)p * VSZ + (size_t)mt * 128 * 512;
        wsrc = g_wU[2 * b] + ((size_t)(p * 256) + o * 128) * 256;
        mdst = g_Mz[b] + ((size_t)mt * 128) * 4096 + p * 256 + o * 128;
    }

    float acc[4][8][4];
#pragma unroll
    for (int t = 0; t < 4; t++)
#pragma unroll
        for (int j = 0; j < 8; j++)
#pragma unroll
            for (int e = 0; e < 4; e++) acc[t][j][e] = 0.f;

    auto copyAB = [&](int g) {
        const int buf = g & 1, c0 = g * 32;
#pragma unroll
        for (int k = 0; k < 8; k++) {                // A: 1024 cp16 (hi+lo)
            int id = tid + k * 128;
            int row = id >> 3, part = id & 7, comp = part >> 2, kq = part & 3;
            cp16(sBu + buf * ABUF + row * ASTR + comp * 64 + kq * 16,
                 vsrc + (size_t)row * 512 + comp * 256 + c0 + kq * 8);
        }
#pragma unroll
        for (int k = 0; k < 4; k++) {                // B: 512 cp16 (single)
            int id = tid + k * 128;
            int row = id >> 2, part = id & 3;
            cp16(sBu + BOFF + buf * BBUF + row * BSTR + part * 16,
                 wsrc + (size_t)row * 256 + c0 + part * 8);
        }
        cp_commit();
    };

    copyAB(0);
#pragma unroll 1
    for (int g = 0; g < 8; g++) {
        const int buf = g & 1;
        __syncthreads();
        if (g + 1 < 8) { copyAB(g + 1); cp_wait<1>(); }
        else           { cp_wait<0>(); }
        __syncthreads();

        uint32_t aaddr[4], baddr[4];
#pragma unroll
        for (int t = 0; t < 4; t++) {
            int m = warp_m * 64 + t * 16 + (lid & 7) + ((lid >> 3) & 1) * 8;
            aaddr[t] = sBu + buf * ABUF + m * ASTR + ((lid >> 4) << 4);
        }
#pragma unroll
        for (int j = 0; j < 4; j++) {
            int n = warp_n * 64 + j * 16 + (lid & 7) + (lid >> 4) * 8;
            baddr[j] = sBu + BOFF + buf * BBUF + n * BSTR + (((lid >> 3) & 1) << 4);
        }

#pragma unroll
        for (int ks = 0; ks < 2; ks++) {
            uint32_t ah[4][4], al[4][4], bq[4][4];
#pragma unroll
            for (int t = 0; t < 4; t++) LDSM4(ah[t], aaddr[t] + ks * 32);
#pragma unroll
            for (int t = 0; t < 4; t++) LDSM4(al[t], aaddr[t] + ks * 32 + 64);
#pragma unroll
            for (int j = 0; j < 4; j++) LDSM4(bq[j], baddr[j] + ks * 32);
            // hi*B
#pragma unroll
            for (int t = 0; t < 4; t++)
#pragma unroll
                for (int j = 0; j < 4; j++) {
                    MMA(acc[t][2 * j],     ah[t], bq[j][0], bq[j][1]);
                    MMA(acc[t][2 * j + 1], ah[t], bq[j][2], bq[j][3]);
                }
            // lo*B
#pragma unroll
            for (int t = 0; t < 4; t++)
#pragma unroll
                for (int j = 0; j < 4; j++) {
                    MMA(acc[t][2 * j],     al[t], bq[j][0], bq[j][1]);
                    MMA(acc[t][2 * j + 1], al[t], bq[j][2], bq[j][3]);
                }
        }
    }

    // epilogue: [tile][pos][oc] stores; tile stride 4096 floats
#pragma unroll
    for (int t = 0; t < 4; t++) {
        int r = warp_m * 64 + t * 16 + (lid >> 2);
#pragma unroll
        for (int jj = 0; jj < 8; jj++) {
            int c = warp_n * 64 + (jj >> 1) * 16 + (jj & 1) * 8 + (lid & 3) * 2;
            float* base = mdst + (size_t)r * 4096 + c;
            *(float2*)base = make_float2(acc[t][jj][0], acc[t][jj][1]);
            *(float2*)(base + (size_t)8 * 4096) = make_float2(acc[t][jj][2], acc[t][jj][3]);
        }
    }
}

// ============================ inverse transforms =============================
__global__ __launch_bounds__(256)
void inv_x() {
    __shared__ float sOut[64][60];
    __shared__ float sB[64];
    const int ocg = blockIdx.x * 64;
    const int ty  = blockIdx.y;
    const int img = blockIdx.z & 31, b = blockIdx.z >> 5;
    const int tid = threadIdx.x;
    if (tid < 64) sB[tid] = g_bias[1 + 2 * b][ocg + tid];
    __syncthreads();

    const float* Mb = g_M[b];
#pragma unroll
    for (int k = 0; k < 4; k++) {
        int it = k * 256 + tid;                      // 960 items: tx(15) x oc(64)
        if (it < 960) {
            int tx = it >> 6, oc = it & 63;
            size_t gt = (size_t)img * 225 + ty * 15 + tx;
            const float* mp = Mb + gt * 4096 + ocg + oc;
            float Mv[16];
#pragma unroll
            for (int pos = 0; pos < 16; pos++) Mv[pos] = mp[pos * 256];
            float t0[4], t1[4];
#pragma unroll
            for (int j = 0; j < 4; j++) {
                t0[j] = Mv[j] + Mv[4 + j] + Mv[8 + j];
                t1[j] = Mv[4 + j] - Mv[8 + j] - Mv[12 + j];
            }
            float bs = sB[oc];
            sOut[oc][tx * 2]          = t0[0] + t0[1] + t0[2] + bs;
            sOut[oc][tx * 2 + 1]      = t0[1] - t0[2] - t0[3] + bs;
            sOut[oc][30 + tx * 2]     = t1[0] + t1[1] + t1[2] + bs;
            sOut[oc][30 + tx * 2 + 1] = t1[1] - t1[2] - t1[3] + bs;
        }
    }
    __syncthreads();
    float* dst = g_xf[b] + ((size_t)img * 256 + ocg) * 900 + (2 * ty) * 30;
#pragma unroll
    for (int k = 0; k < 15; k++) {
        int f = k * 256 + tid;                       // 3840 floats
        int oc = f / 60, rem = f - oc * 60;
        dst[(size_t)oc * 900 + rem] = sOut[oc][rem];
    }
}

__global__ __launch_bounds__(256)
void inv_z() {
    __shared__ float sOut[256 * 36];
    const int img = blockIdx.x, b = blockIdx.y;
    const int oc = threadIdx.x;
    const float bs = g_bias[2 * b][oc];
    const float* Mb = g_Mz[b];
#pragma unroll
    for (int t = 0; t < 9; t++) {
        int ty = t / 3, tx = t - ty * 3;
        const float* mp = Mb + ((size_t)img * 9 + t) * 4096 + oc;
        float Mv[16];
#pragma unroll
        for (int pos = 0; pos < 16; pos++) Mv[pos] = mp[pos * 256];
        float t0[4], t1[4];
#pragma unroll
        for (int j = 0; j < 4; j++) {
            t0[j] = Mv[j] + Mv[4 + j] + Mv[8 + j];
            t1[j] = Mv[4 + j] - Mv[8 + j] - Mv[12 + j];
        }
        sOut[oc * 36 + (2 * ty) * 6 + 2 * tx]         = t0[0] + t0[1] + t0[2] + bs;
        sOut[oc * 36 + (2 * ty) * 6 + 2 * tx + 1]     = t0[1] - t0[2] - t0[3] + bs;
        sOut[oc * 36 + (2 * ty + 1) * 6 + 2 * tx]     = t1[0] + t1[1] + t1[2] + bs;
        sOut[oc * 36 + (2 * ty + 1) * 6 + 2 * tx + 1] = t1[1] - t1[2] - t1[3] + bs;
    }
    __syncthreads();
    float* dst = g_zf[b] + (size_t)img * 256 * 36;
#pragma unroll
    for (int k = 0; k < 36; k++) {
        int f = k * 256 + threadIdx.x;
        dst[f] = sOut[f];
    }
}

// ============================ depthwise xcorr ================================
__global__ __launch_bounds__(640)
void xcorr_kernel(float* __restrict__ out) {
    __shared__ float s_x[900];
    __shared__ float s_z[36];
    const int branch = blockIdx.y;
    const int bc = blockIdx.x;
    const int tid = threadIdx.x;
    if (tid < 36) s_z[tid] = g_zf[branch][(size_t)bc * 36 + tid];
    for (int i = tid; i < 900; i += 640) s_x[i] = g_xf[branch][(size_t)bc * 900 + i];
    __syncthreads();
    if (tid < 625) {
        int oy = tid / 25, ox = tid % 25;
        float s = 0.f;
#pragma unroll
        for (int u = 0; u < 6; u++)
#pragma unroll
            for (int v = 0; v < 6; v++)
                s = fmaf(s_z[u * 6 + v], s_x[(oy + u) * 30 + ox + v], s);
        out[(size_t)branch * OSZ + (size_t)bc * 625 + tid] = s;
    }
}

// ============================ launch =========================================
extern "C" void kernel_launch(void* const* d_in, const int* in_sizes, int n_in,
                              void* d_out, int out_size) {
    const float* z = (const float*)d_in[0];
    const float* x = (const float*)d_in[1];

    PrepArgs pa;
    for (int p = 0; p < 4; p++) {
        pa.w[p] = (const float*)d_in[2 + p * 5 + 0];
        pa.g[p] = (const float*)d_in[2 + p * 5 + 1];
        pa.b[p] = (const float*)d_in[2 + p * 5 + 2];
        pa.m[p] = (const float*)d_in[2 + p * 5 + 3];
        pa.v[p] = (const float*)d_in[2 + p * 5 + 4];
    }

    cudaFuncSetAttribute(wino_gemm,
                         cudaFuncAttributeMaxDynamicSharedMemorySize, GEMM_SMEM);
    cudaFuncSetAttribute(wino_gemm,
                         cudaFuncAttributePreferredSharedMemoryCarveout, 100);

    prep_kernel<<<1024, 256>>>(pa);
    xform_x<<<dim3(32, 32), 256>>>(x);
    xform_z<<<dim3(32, 32), 128>>>(z);
    wino_gemm<<<3840, 128, GEMM_SMEM>>>();
    inv_x<<<dim3(4, 15, 64), 256>>>();
    inv_z<<<dim3(32, 2), 256>>>();
    xcorr_kernel<<<dim3(NB * COUT, 2), 640>>>((float*)d_out);
}

// round 10
// speedup vs baseline: 1.5198x; 1.1081x over previous
#include <cuda_runtime.h>
#include <cuda_fp16.h>
#include <cstdint>

#define CIN 256
#define COUT 256
#define NB 32
#define ZSZ (NB * COUT * 36)
#define XSZ (NB * COUT * 900)
#define OSZ (NB * COUT * 625)

// Winograd tile counts: x: 15x15*32 = 7200 (pad 7296 = 228*32), z: 288 (pad 384)
#define NTX 7296
#define NTZ 384
#define VSX ((size_t)NTX * 512)
#define VSZ ((size_t)NTZ * 512)

__device__ __align__(16) __half g_wU[4][16 * 256 * 256]; // [path][(pos*256+oc)*256 + cin]
__device__ float g_bias[4][COUT];
__device__ __align__(16) __half g_V[16 * NTX * 512];     // [pos][tile][comp*256+cin]
__device__ __align__(16) __half g_Vz[16 * NTZ * 512];
__device__ float g_M[2][(size_t)NTX * 16 * 256];         // [branch][tile][pos][oc]
__device__ float g_Mz[2][(size_t)NTZ * 16 * 256];
__device__ float g_zf[2][ZSZ];
__device__ float g_xf[2][XSZ];

struct PrepArgs {
    const float* w[4];
    const float* g[4];
    const float* b[4];
    const float* m[4];
    const float* v[4];
};

// ============================ helpers ========================================
__device__ __forceinline__ uint32_t smem_u32(const void* p) {
    uint32_t a;
    asm("{ .reg .u64 t; cvta.to.shared.u64 t, %1; cvt.u32.u64 %0, t; }"
        : "=r"(a) : "l"(p));
    return a;
}
__device__ __forceinline__ void cp16(uint32_t dst, const void* src) {
    asm volatile("cp.async.cg.shared.global [%0], [%1], 16;" :: "r"(dst), "l"(src));
}
__device__ __forceinline__ void cp_commit() {
    asm volatile("cp.async.commit_group;" ::: "memory");
}
template <int N>
__device__ __forceinline__ void cp_wait() {
    asm volatile("cp.async.wait_group %0;" :: "n"(N) : "memory");
}

#define LDSM4(r, addr)                                                         \
    asm volatile("ldmatrix.sync.aligned.m8n8.x4.shared.b16 {%0,%1,%2,%3},[%4];"\
        : "=r"((r)[0]), "=r"((r)[1]), "=r"((r)[2]), "=r"((r)[3]) : "r"(addr))

#define MMA(d, a, b0, b1)                                                      \
    asm volatile("mma.sync.aligned.m16n8k16.row.col.f32.f16.f16.f32 "          \
        "{%0,%1,%2,%3}, {%4,%5,%6,%7}, {%8,%9}, {%0,%1,%2,%3};"                \
        : "+f"((d)[0]), "+f"((d)[1]), "+f"((d)[2]), "+f"((d)[3])               \
        : "r"((a)[0]), "r"((a)[1]), "r"((a)[2]), "r"((a)[3]),                  \
          "r"(b0), "r"(b1))

__device__ __forceinline__ void hsplit(float v, __half& hi, __half& lo) {
    hi = __float2half_rn(v);
    lo = __float2half_rn(v - __half2float(hi));
}

// ============================ prep: weight transform =========================
__global__ void prep_kernel(PrepArgs a) {
    int i = blockIdx.x * blockDim.x + threadIdx.x;       // 262144 items
    int path = i >> 16;
    int oc   = (i >> 8) & 255;
    int cin  = i & 255;
    float inv = a.g[path][oc] * rsqrtf(a.v[path][oc] + 1e-5f);
    const float* wp = a.w[path] + oc * 2304 + cin * 9;
    float w[3][3];
#pragma unroll
    for (int r = 0; r < 3; r++)
#pragma unroll
        for (int c = 0; c < 3; c++) w[r][c] = wp[r * 3 + c] * inv;

    float T[4][3];
#pragma unroll
    for (int j = 0; j < 3; j++) {
        T[0][j] = w[0][j];
        T[1][j] = 0.5f * (w[0][j] + w[1][j] + w[2][j]);
        T[2][j] = 0.5f * (w[0][j] - w[1][j] + w[2][j]);
        T[3][j] = w[2][j];
    }
#pragma unroll
    for (int r = 0; r < 4; r++) {
        float U[4];
        U[0] = T[r][0];
        U[1] = 0.5f * (T[r][0] + T[r][1] + T[r][2]);
        U[2] = 0.5f * (T[r][0] - T[r][1] + T[r][2]);
        U[3] = T[r][2];
#pragma unroll
        for (int c = 0; c < 4; c++)
            g_wU[path][((size_t)((r * 4 + c) * 256 + oc)) * 256 + cin] =
                __float2half_rn(U[c]);
    }
    if (i < 1024) {
        int p2 = i >> 8, oc2 = i & 255;
        float inv2 = a.g[p2][oc2] * rsqrtf(a.v[p2][oc2] + 1e-5f);
        g_bias[p2][oc2] = a.b[p2][oc2] - a.m[p2][oc2] * inv2;
    }
}

// ============================ input transforms ===============================
__device__ __forceinline__ void wino_fwd(const float d[4][4], float V[4][4]) {
    float t[4][4];
#pragma unroll
    for (int j = 0; j < 4; j++) {
        t[0][j] = d[0][j] - d[2][j];
        t[1][j] = d[1][j] + d[2][j];
        t[2][j] = d[2][j] - d[1][j];
        t[3][j] = d[1][j] - d[3][j];
    }
#pragma unroll
    for (int i = 0; i < 4; i++) {
        V[i][0] = t[i][0] - t[i][2];
        V[i][1] = t[i][1] + t[i][2];
        V[i][2] = t[i][2] - t[i][1];
        V[i][3] = t[i][1] - t[i][3];
    }
}

// Block = (img, cg of 64 cins, ty). Loads 4 rows x 32 cols x 64 cins,
// transforms 15 tiles, stages V in smem, writes 128B-contiguous runs.
#define SDSTR 129
#define XF_SD_BYTES (64 * SDSTR * 4)                 // 33024
#define XF_SV_OFF   XF_SD_BYTES
#define XF_SMEM (XF_SD_BYTES + 15 * 16 * 2 * 64 * 2) // 94464

__global__ __launch_bounds__(256)
void xform_x(const float* __restrict__ x) {
    extern __shared__ __align__(16) char xsm[];
    float* sd = (float*)xsm;
    __half* sV = (__half*)(xsm + XF_SV_OFF);         // [tile][pos][comp][64]
    const int img = blockIdx.x, cg = blockIdx.y, ty = blockIdx.z;
    const int tid = threadIdx.x;
    const int c0 = cg * 64;
    const float* src = x + ((size_t)img * 256 + c0) * 1024 + 2 * ty * 32;

#pragma unroll
    for (int k = 0; k < 32; k++) {                   // 8192 floats, coalesced
        int id = k * 256 + tid;
        int c = id >> 7, rc = id & 127;
        sd[c * SDSTR + rc] = src[(size_t)c * 1024 + rc];
    }
    __syncthreads();

#pragma unroll
    for (int k = 0; k < 4; k++) {                    // 960 (tx, cin) items
        int id = k * 256 + tid;
        if (id < 960) {
            int tx = id >> 6, c = id & 63;
            const float* p = sd + c * SDSTR + 2 * tx;
            float d[4][4], V[4][4];
#pragma unroll
            for (int i = 0; i < 4; i++)
#pragma unroll
                for (int j = 0; j < 4; j++) d[i][j] = p[i * 32 + j];
            wino_fwd(d, V);
#pragma unroll
            for (int i = 0; i < 4; i++)
#pragma unroll
                for (int j = 0; j < 4; j++) {
                    __half hi, lo;
                    hsplit(V[i][j], hi, lo);
                    int pb = (tx * 16 + (i * 4 + j)) * 128;
                    sV[pb + c]      = hi;
                    sV[pb + 64 + c] = lo;
                }
        }
    }
    __syncthreads();

#pragma unroll
    for (int k = 0; k < 15; k++) {                   // exactly 3840 uint4
        int id = k * 256 + tid;
        int q    = id & 7;
        int comp = (id >> 3) & 1;
        int pos  = (id >> 4) & 15;
        int tile = id >> 8;
        uint4 v = *(const uint4*)(sV + ((tile * 16 + pos) * 2 + comp) * 64 + q * 8);
        *(uint4*)(g_V + (size_t)pos * VSX +
                  ((size_t)img * 225 + ty * 15 + tile) * 512 +
                  comp * 256 + c0 + q * 8) = v;
    }
}

__global__ __launch_bounds__(128)
void xform_z(const float* __restrict__ z) {
    __shared__ float sd[8][64];
    __shared__ __align__(16) __half sVz[9][16][2][8];
    const int img = blockIdx.x, cg = blockIdx.y, tid = threadIdx.x;
    const float* src = z + ((size_t)img * 256 + cg * 8) * 64;
#pragma unroll
    for (int k = 0; k < 4; k++) {
        int lin = k * 128 + tid;
        sd[lin >> 6][lin & 63] = src[lin];
    }
    __syncthreads();
    if (tid < 72) {
        int tl = tid >> 3, c = tid & 7;
        int ty = tl / 3, tx = tl - ty * 3;
        float d[4][4], V[4][4];
#pragma unroll
        for (int i = 0; i < 4; i++)
#pragma unroll
            for (int j = 0; j < 4; j++)
                d[i][j] = sd[c][(2 * ty + i) * 8 + 2 * tx + j];
        wino_fwd(d, V);
#pragma unroll
        for (int i = 0; i < 4; i++)
#pragma unroll
            for (int j = 0; j < 4; j++) {
                __half hi, lo;
                hsplit(V[i][j], hi, lo);
                sVz[tl][i * 4 + j][0][c] = hi;
                sVz[tl][i * 4 + j][1][c] = lo;
            }
    }
    __syncthreads();
#pragma unroll
    for (int k = 0; k < 3; k++) {
        int cid = k * 128 + tid;
        if (cid < 288) {
            int tl = cid >> 5, pos = (cid >> 1) & 15, comp = cid & 1;
            uint4 val = *(const uint4*)&sVz[tl][pos][comp][0];
            *(uint4*)(g_Vz + (size_t)pos * VSZ +
                      ((size_t)img * 9 + tl) * 512 + comp * 256 + cg * 8) = val;
        }
    }
}

// ============================ batched GEMM ===================================
// D[128 tile, 128 oc] = V[128,256] * U[128,256]^T, 2-term fp16 A split.
// x blocks: bid = ((b*16+p)*57 + mt)*2 + o  (adjacent o-pair shares A -> L2)
#define ASTR 144u
#define ABUF (128u * ASTR)        // 18432
#define BSTR 80u
#define BBUF (128u * BSTR)        // 10240
#define BOFF (2u * ABUF)          // 36864
#define GEMM_SMEM (BOFF + 2u * BBUF)   // 57344

__global__ __launch_bounds__(128, 2)
void wino_gemm() {
    extern __shared__ __align__(16) char smem[];
    const int tid = threadIdx.x, lid = tid & 31, wid = tid >> 5;
    const int warp_m = wid >> 1, warp_n = wid & 1;
    const uint32_t sBu = smem_u32(smem);

    const int bid = blockIdx.x;
    const __half *vsrc, *wsrc;
    float* mdst;
    if (bid < 3648) {
        int o = bid & 1;
        int pair = bid >> 1;       // 0..1823
        int mt = pair % 57;
        int rest = pair / 57;      // 0..31
        int p = rest & 15, b = rest >> 4;
        vsrc = g_V + (size_t)p * VSX + (size_t)mt * 128 * 512;
        wsrc = g_wU[1 + 2 * b] + ((size_t)(p * 256) + o * 128) * 256;
        mdst = g_M[b] + ((size_t)mt * 128) * 4096 + p * 256 + o * 128;
    } else {
        int zb = bid - 3648;
        int q = zb / 3, mt = zb - q * 3;
        int p = q & 15; q >>= 4;
        int o = q & 1, b = q >> 1;
        vsrc = g_Vz + (size_t)p * VSZ + (size_t)mt * 128 * 512;
        wsrc = g_wU[2 * b] + ((size_t)(p * 256) + o * 128) * 256;
        mdst = g_Mz[b] + ((size_t)mt * 128) * 4096 + p * 256 + o * 128;
    }

    float acc[4][8][4];
#pragma unroll
    for (int t = 0; t < 4; t++)
#pragma unroll
        for (int j = 0; j < 8; j++)
#pragma unroll
            for (int e = 0; e < 4; e++) acc[t][j][e] = 0.f;

    auto copyAB = [&](int g) {
        const int buf = g & 1, c0 = g * 32;
#pragma unroll
        for (int k = 0; k < 8; k++) {                // A: 1024 cp16 (hi+lo)
            int id = tid + k * 128;
            int row = id >> 3, part = id & 7, comp = part >> 2, kq = part & 3;
            cp16(sBu + buf * ABUF + row * ASTR + comp * 64 + kq * 16,
                 vsrc + (size_t)row * 512 + comp * 256 + c0 + kq * 8);
        }
#pragma unroll
        for (int k = 0; k < 4; k++) {                // B: 512 cp16
            int id = tid + k * 128;
            int row = id >> 2, part = id & 3;
            cp16(sBu + BOFF + buf * BBUF + row * BSTR + part * 16,
                 wsrc + (size_t)row * 256 + c0 + part * 8);
        }
        cp_commit();
    };

    copyAB(0);
#pragma unroll 1
    for (int g = 0; g < 8; g++) {
        const int buf = g & 1;
        __syncthreads();
        if (g + 1 < 8) { copyAB(g + 1); cp_wait<1>(); }
        else           { cp_wait<0>(); }
        __syncthreads();

        uint32_t aaddr[4], baddr[4];
#pragma unroll
        for (int t = 0; t < 4; t++) {
            int m = warp_m * 64 + t * 16 + (lid & 7) + ((lid >> 3) & 1) * 8;
            aaddr[t] = sBu + buf * ABUF + m * ASTR + ((lid >> 4) << 4);
        }
#pragma unroll
        for (int j = 0; j < 4; j++) {
            int n = warp_n * 64 + j * 16 + (lid & 7) + (lid >> 4) * 8;
            baddr[j] = sBu + BOFF + buf * BBUF + n * BSTR + (((lid >> 3) & 1) << 4);
        }

#pragma unroll
        for (int ks = 0; ks < 2; ks++) {
            uint32_t ah[4][4], al[4][4], bq[4][4];
#pragma unroll
            for (int t = 0; t < 4; t++) LDSM4(ah[t], aaddr[t] + ks * 32);
#pragma unroll
            for (int t = 0; t < 4; t++) LDSM4(al[t], aaddr[t] + ks * 32 + 64);
#pragma unroll
            for (int j = 0; j < 4; j++) LDSM4(bq[j], baddr[j] + ks * 32);
            // hi*B
#pragma unroll
            for (int t = 0; t < 4; t++)
#pragma unroll
                for (int j = 0; j < 4; j++) {
                    MMA(acc[t][2 * j],     ah[t], bq[j][0], bq[j][1]);
                    MMA(acc[t][2 * j + 1], ah[t], bq[j][2], bq[j][3]);
                }
            // lo*B
#pragma unroll
            for (int t = 0; t < 4; t++)
#pragma unroll
                for (int j = 0; j < 4; j++) {
                    MMA(acc[t][2 * j],     al[t], bq[j][0], bq[j][1]);
                    MMA(acc[t][2 * j + 1], al[t], bq[j][2], bq[j][3]);
                }
        }
    }

    // epilogue: [tile][pos][oc] stores; tile stride 4096 floats
#pragma unroll
    for (int t = 0; t < 4; t++) {
        int r = warp_m * 64 + t * 16 + (lid >> 2);
#pragma unroll
        for (int jj = 0; jj < 8; jj++) {
            int c = warp_n * 64 + (jj >> 1) * 16 + (jj & 1) * 8 + (lid & 3) * 2;
            float* base = mdst + (size_t)r * 4096 + c;
            *(float2*)base = make_float2(acc[t][jj][0], acc[t][jj][1]);
            *(float2*)(base + (size_t)8 * 4096) = make_float2(acc[t][jj][2], acc[t][jj][3]);
        }
    }
}

// ============================ inverse transforms =============================
__global__ __launch_bounds__(256)
void inv_x() {
    __shared__ float sOut[64][60];
    __shared__ float sB[64];
    const int ocg = blockIdx.x * 64;
    const int ty  = blockIdx.y;
    const int img = blockIdx.z & 31, b = blockIdx.z >> 5;
    const int tid = threadIdx.x;
    if (tid < 64) sB[tid] = g_bias[1 + 2 * b][ocg + tid];
    __syncthreads();

    const float* Mb = g_M[b];
#pragma unroll
    for (int k = 0; k < 4; k++) {
        int it = k * 256 + tid;                      // 960: tx(15) x oc(64)
        if (it < 960) {
            int tx = it >> 6, oc = it & 63;
            size_t gt = (size_t)img * 225 + ty * 15 + tx;
            const float* mp = Mb + gt * 4096 + ocg + oc;
            float Mv[16];
#pragma unroll
            for (int pos = 0; pos < 16; pos++) Mv[pos] = mp[pos * 256];
            float t0[4], t1[4];
#pragma unroll
            for (int j = 0; j < 4; j++) {
                t0[j] = Mv[j] + Mv[4 + j] + Mv[8 + j];
                t1[j] = Mv[4 + j] - Mv[8 + j] - Mv[12 + j];
            }
            float bs = sB[oc];
            sOut[oc][tx * 2]          = t0[0] + t0[1] + t0[2] + bs;
            sOut[oc][tx * 2 + 1]      = t0[1] - t0[2] - t0[3] + bs;
            sOut[oc][30 + tx * 2]     = t1[0] + t1[1] + t1[2] + bs;
            sOut[oc][30 + tx * 2 + 1] = t1[1] - t1[2] - t1[3] + bs;
        }
    }
    __syncthreads();
    float* dst = g_xf[b] + ((size_t)img * 256 + ocg) * 900 + (2 * ty) * 30;
#pragma unroll
    for (int k = 0; k < 15; k++) {
        int f = k * 256 + tid;
        int oc = f / 60, rem = f - oc * 60;
        dst[(size_t)oc * 900 + rem] = sOut[oc][rem];
    }
}

__global__ __launch_bounds__(256)
void inv_z() {
    __shared__ float sOut[256 * 36];
    const int img = blockIdx.x, b = blockIdx.y;
    const int oc = threadIdx.x;
    const float bs = g_bias[2 * b][oc];
    const float* Mb = g_Mz[b];
#pragma unroll
    for (int t = 0; t < 9; t++) {
        int ty = t / 3, tx = t - ty * 3;
        const float* mp = Mb + ((size_t)img * 9 + t) * 4096 + oc;
        float Mv[16];
#pragma unroll
        for (int pos = 0; pos < 16; pos++) Mv[pos] = mp[pos * 256];
        float t0[4], t1[4];
#pragma unroll
        for (int j = 0; j < 4; j++) {
            t0[j] = Mv[j] + Mv[4 + j] + Mv[8 + j];
            t1[j] = Mv[4 + j] - Mv[8 + j] - Mv[12 + j];
        }
        sOut[oc * 36 + (2 * ty) * 6 + 2 * tx]         = t0[0] + t0[1] + t0[2] + bs;
        sOut[oc * 36 + (2 * ty) * 6 + 2 * tx + 1]     = t0[1] - t0[2] - t0[3] + bs;
        sOut[oc * 36 + (2 * ty + 1) * 6 + 2 * tx]     = t1[0] + t1[1] + t1[2] + bs;
        sOut[oc * 36 + (2 * ty + 1) * 6 + 2 * tx + 1] = t1[1] - t1[2] - t1[3] + bs;
    }
    __syncthreads();
    float* dst = g_zf[b] + (size_t)img * 256 * 36;
#pragma unroll
    for (int k = 0; k < 36; k++) {
        int f = k * 256 + threadIdx.x;
        dst[f] = sOut[f];
    }
}

// ============================ depthwise xcorr ================================
__global__ __launch_bounds__(640)
void xcorr_kernel(float* __restrict__ out) {
    __shared__ float s_x[900];
    __shared__ float s_z[36];
    const int branch = blockIdx.y;
    const int bc = blockIdx.x;
    const int tid = threadIdx.x;
    if (tid < 36) s_z[tid] = g_zf[branch][(size_t)bc * 36 + tid];
    for (int i = tid; i < 900; i += 640) s_x[i] = g_xf[branch][(size_t)bc * 900 + i];
    __syncthreads();
    if (tid < 625) {
        int oy = tid / 25, ox = tid % 25;
        float s = 0.f;
#pragma unroll
        for (int u = 0; u < 6; u++)
#pragma unroll
            for (int v = 0; v < 6; v++)
                s = fmaf(s_z[u * 6 + v], s_x[(oy + u) * 30 + ox + v], s);
        out[(size_t)branch * OSZ + (size_t)bc * 625 + tid] = s;
    }
}

// ============================ launch =========================================
extern "C" void kernel_launch(void* const* d_in, const int* in_sizes, int n_in,
                              void* d_out, int out_size) {
    const float* z = (const float*)d_in[0];
    const float* x = (const float*)d_in[1];

    PrepArgs pa;
    for (int p = 0; p < 4; p++) {
        pa.w[p] = (const float*)d_in[2 + p * 5 + 0];
        pa.g[p] = (const float*)d_in[2 + p * 5 + 1];
        pa.b[p] = (const float*)d_in[2 + p * 5 + 2];
        pa.m[p] = (const float*)d_in[2 + p * 5 + 3];
        pa.v[p] = (const float*)d_in[2 + p * 5 + 4];
    }

    cudaFuncSetAttribute(wino_gemm,
                         cudaFuncAttributeMaxDynamicSharedMemorySize, GEMM_SMEM);
    cudaFuncSetAttribute(wino_gemm,
                         cudaFuncAttributePreferredSharedMemoryCarveout, 100);
    cudaFuncSetAttribute(xform_x,
                         cudaFuncAttributeMaxDynamicSharedMemorySize, XF_SMEM);

    prep_kernel<<<1024, 256>>>(pa);
    xform_x<<<dim3(32, 4, 15), 256, XF_SMEM>>>(x);
    xform_z<<<dim3(32, 32), 128>>>(z);
    wino_gemm<<<3840, 128, GEMM_SMEM>>>();
    inv_x<<<dim3(4, 15, 64), 256>>>();
    inv_z<<<dim3(32, 2), 256>>>();
    xcorr_kernel<<<dim3(NB * COUT, 2), 640>>>((float*)d_out);
}

// round 11
// speedup vs baseline: 1.6785x; 1.1045x over previous
#include <cuda_runtime.h>
#include <cuda_fp16.h>
#include <cstdint>

#define CIN 256
#define COUT 256
#define NB 32
#define ZSZ (NB * COUT * 36)
#define OSZ (NB * COUT * 625)

// Winograd tile counts: x: 15x15*32 = 7200 (pad 7296 = 228*32), z: 288 (pad 384)
#define NTX 7296
#define NTZ 384
#define VSX ((size_t)NTX * 512)
#define VSZ ((size_t)NTZ * 512)

__device__ __align__(16) __half g_wU[4][16 * 256 * 256]; // [path][(pos*256+oc)*256 + cin]
__device__ float g_bias[4][COUT];
__device__ __align__(16) __half g_V[16 * NTX * 512];     // [pos][tile][comp*256+cin]
__device__ __align__(16) __half g_Vz[16 * NTZ * 512];
__device__ float g_M[2][(size_t)NTX * 16 * 256];         // [branch][tile][pos][oc]
__device__ float g_Mz[2][(size_t)NTZ * 16 * 256];
__device__ float g_zf[2][ZSZ];

struct PrepArgs {
    const float* w[4];
    const float* g[4];
    const float* b[4];
    const float* m[4];
    const float* v[4];
};

// ============================ helpers ========================================
__device__ __forceinline__ uint32_t smem_u32(const void* p) {
    uint32_t a;
    asm("{ .reg .u64 t; cvta.to.shared.u64 t, %1; cvt.u32.u64 %0, t; }"
        : "=r"(a) : "l"(p));
    return a;
}
__device__ __forceinline__ void cp16(uint32_t dst, const void* src) {
    asm volatile("cp.async.cg.shared.global [%0], [%1], 16;" :: "r"(dst), "l"(src));
}
__device__ __forceinline__ void cp_commit() {
    asm volatile("cp.async.commit_group;" ::: "memory");
}
template <int N>
__device__ __forceinline__ void cp_wait() {
    asm volatile("cp.async.wait_group %0;" :: "n"(N) : "memory");
}

#define LDSM4(r, addr)                                                         \
    asm volatile("ldmatrix.sync.aligned.m8n8.x4.shared.b16 {%0,%1,%2,%3},[%4];"\
        : "=r"((r)[0]), "=r"((r)[1]), "=r"((r)[2]), "=r"((r)[3]) : "r"(addr))

#define MMA(d, a, b0, b1)                                                      \
    asm volatile("mma.sync.aligned.m16n8k16.row.col.f32.f16.f16.f32 "          \
        "{%0,%1,%2,%3}, {%4,%5,%6,%7}, {%8,%9}, {%0,%1,%2,%3};"                \
        : "+f"((d)[0]), "+f"((d)[1]), "+f"((d)[2]), "+f"((d)[3])               \
        : "r"((a)[0]), "r"((a)[1]), "r"((a)[2]), "r"((a)[3]),                  \
          "r"(b0), "r"(b1))

__device__ __forceinline__ void hsplit(float v, __half& hi, __half& lo) {
    hi = __float2half_rn(v);
    lo = __float2half_rn(v - __half2float(hi));
}

// ============================ prep: weight transform =========================
__global__ void prep_kernel(PrepArgs a) {
    int i = blockIdx.x * blockDim.x + threadIdx.x;       // 262144 items
    int path = i >> 16;
    int oc   = (i >> 8) & 255;
    int cin  = i & 255;
    float inv = a.g[path][oc] * rsqrtf(a.v[path][oc] + 1e-5f);
    const float* wp = a.w[path] + oc * 2304 + cin * 9;
    float w[3][3];
#pragma unroll
    for (int r = 0; r < 3; r++)
#pragma unroll
        for (int c = 0; c < 3; c++) w[r][c] = wp[r * 3 + c] * inv;

    float T[4][3];
#pragma unroll
    for (int j = 0; j < 3; j++) {
        T[0][j] = w[0][j];
        T[1][j] = 0.5f * (w[0][j] + w[1][j] + w[2][j]);
        T[2][j] = 0.5f * (w[0][j] - w[1][j] + w[2][j]);
        T[3][j] = w[2][j];
    }
#pragma unroll
    for (int r = 0; r < 4; r++) {
        float U[4];
        U[0] = T[r][0];
        U[1] = 0.5f * (T[r][0] + T[r][1] + T[r][2]);
        U[2] = 0.5f * (T[r][0] - T[r][1] + T[r][2]);
        U[3] = T[r][2];
#pragma unroll
        for (int c = 0; c < 4; c++)
            g_wU[path][((size_t)((r * 4 + c) * 256 + oc)) * 256 + cin] =
                __float2half_rn(U[c]);
    }
    if (i < 1024) {
        int p2 = i >> 8, oc2 = i & 255;
        float inv2 = a.g[p2][oc2] * rsqrtf(a.v[p2][oc2] + 1e-5f);
        g_bias[p2][oc2] = a.b[p2][oc2] - a.m[p2][oc2] * inv2;
    }
}

// ============================ input transforms ===============================
__device__ __forceinline__ void wino_fwd(const float d[4][4], float V[4][4]) {
    float t[4][4];
#pragma unroll
    for (int j = 0; j < 4; j++) {
        t[0][j] = d[0][j] - d[2][j];
        t[1][j] = d[1][j] + d[2][j];
        t[2][j] = d[2][j] - d[1][j];
        t[3][j] = d[1][j] - d[3][j];
    }
#pragma unroll
    for (int i = 0; i < 4; i++) {
        V[i][0] = t[i][0] - t[i][2];
        V[i][1] = t[i][1] + t[i][2];
        V[i][2] = t[i][2] - t[i][1];
        V[i][3] = t[i][1] - t[i][3];
    }
}

#define SDSTR 129
#define XF_SD_BYTES (64 * SDSTR * 4)                 // 33024
#define XF_SV_OFF   XF_SD_BYTES
#define XF_SMEM (XF_SD_BYTES + 15 * 16 * 2 * 64 * 2) // 94464

__global__ __launch_bounds__(256)
void xform_x(const float* __restrict__ x) {
    extern __shared__ __align__(16) char xsm[];
    float* sd = (float*)xsm;
    __half* sV = (__half*)(xsm + XF_SV_OFF);         // [tile][pos][comp][64]
    const int img = blockIdx.x, cg = blockIdx.y, ty = blockIdx.z;
    const int tid = threadIdx.x;
    const int c0 = cg * 64;
    const float* src = x + ((size_t)img * 256 + c0) * 1024 + 2 * ty * 32;

#pragma unroll
    for (int k = 0; k < 32; k++) {
        int id = k * 256 + tid;
        int c = id >> 7, rc = id & 127;
        sd[c * SDSTR + rc] = src[(size_t)c * 1024 + rc];
    }
    __syncthreads();

#pragma unroll
    for (int k = 0; k < 4; k++) {
        int id = k * 256 + tid;
        if (id < 960) {
            int tx = id >> 6, c = id & 63;
            const float* p = sd + c * SDSTR + 2 * tx;
            float d[4][4], V[4][4];
#pragma unroll
            for (int i = 0; i < 4; i++)
#pragma unroll
                for (int j = 0; j < 4; j++) d[i][j] = p[i * 32 + j];
            wino_fwd(d, V);
#pragma unroll
            for (int i = 0; i < 4; i++)
#pragma unroll
                for (int j = 0; j < 4; j++) {
                    __half hi, lo;
                    hsplit(V[i][j], hi, lo);
                    int pb = (tx * 16 + (i * 4 + j)) * 128;
                    sV[pb + c]      = hi;
                    sV[pb + 64 + c] = lo;
                }
        }
    }
    __syncthreads();

#pragma unroll
    for (int k = 0; k < 15; k++) {                   // exactly 3840 uint4
        int id = k * 256 + tid;
        int q    = id & 7;
        int comp = (id >> 3) & 1;
        int pos  = (id >> 4) & 15;
        int tile = id >> 8;
        uint4 v = *(const uint4*)(sV + ((tile * 16 + pos) * 2 + comp) * 64 + q * 8);
        *(uint4*)(g_V + (size_t)pos * VSX +
                  ((size_t)img * 225 + ty * 15 + tile) * 512 +
                  comp * 256 + c0 + q * 8) = v;
    }
}

__global__ __launch_bounds__(128)
void xform_z(const float* __restrict__ z) {
    __shared__ float sd[8][64];
    __shared__ __align__(16) __half sVz[9][16][2][8];
    const int img = blockIdx.x, cg = blockIdx.y, tid = threadIdx.x;
    const float* src = z + ((size_t)img * 256 + cg * 8) * 64;
#pragma unroll
    for (int k = 0; k < 4; k++) {
        int lin = k * 128 + tid;
        sd[lin >> 6][lin & 63] = src[lin];
    }
    __syncthreads();
    if (tid < 72) {
        int tl = tid >> 3, c = tid & 7;
        int ty = tl / 3, tx = tl - ty * 3;
        float d[4][4], V[4][4];
#pragma unroll
        for (int i = 0; i < 4; i++)
#pragma unroll
            for (int j = 0; j < 4; j++)
                d[i][j] = sd[c][(2 * ty + i) * 8 + 2 * tx + j];
        wino_fwd(d, V);
#pragma unroll
        for (int i = 0; i < 4; i++)
#pragma unroll
            for (int j = 0; j < 4; j++) {
                __half hi, lo;
                hsplit(V[i][j], hi, lo);
                sVz[tl][i * 4 + j][0][c] = hi;
                sVz[tl][i * 4 + j][1][c] = lo;
            }
    }
    __syncthreads();
#pragma unroll
    for (int k = 0; k < 3; k++) {
        int cid = k * 128 + tid;
        if (cid < 288) {
            int tl = cid >> 5, pos = (cid >> 1) & 15, comp = cid & 1;
            uint4 val = *(const uint4*)&sVz[tl][pos][comp][0];
            *(uint4*)(g_Vz + (size_t)pos * VSZ +
                      ((size_t)img * 9 + tl) * 512 + comp * 256 + cg * 8) = val;
        }
    }
}

// ============================ batched GEMM ===================================
// D[128 tile, 128 oc] = V[128,256] * U[128,256]^T, 2-term fp16 A split.
// Single-sync double-buffer pipeline (copy g+1 after the barrier, overlap with
// compute of g).
#define ASTR 144u
#define ABUF (128u * ASTR)        // 18432
#define BSTR 80u
#define BBUF (128u * BSTR)        // 10240
#define BOFF (2u * ABUF)          // 36864
#define GEMM_SMEM (BOFF + 2u * BBUF)   // 57344

__global__ __launch_bounds__(128, 2)
void wino_gemm() {
    extern __shared__ __align__(16) char smem[];
    const int tid = threadIdx.x, lid = tid & 31, wid = tid >> 5;
    const int warp_m = wid >> 1, warp_n = wid & 1;
    const uint32_t sBu = smem_u32(smem);

    const int bid = blockIdx.x;
    const __half *vsrc, *wsrc;
    float* mdst;
    if (bid < 3648) {
        int o = bid & 1;
        int pair = bid >> 1;
        int mt = pair % 57;
        int rest = pair / 57;
        int p = rest & 15, b = rest >> 4;
        vsrc = g_V + (size_t)p * VSX + (size_t)mt * 128 * 512;
        wsrc = g_wU[1 + 2 * b] + ((size_t)(p * 256) + o * 128) * 256;
        mdst = g_M[b] + ((size_t)mt * 128) * 4096 + p * 256 + o * 128;
    } else {
        int zb = bid - 3648;
        int q = zb / 3, mt = zb - q * 3;
        int p = q & 15; q >>= 4;
        int o = q & 1, b = q >> 1;
        vsrc = g_Vz + (size_t)p * VSZ + (size_t)mt * 128 * 512;
        wsrc = g_wU[2 * b] + ((size_t)(p * 256) + o * 128) * 256;
        mdst = g_Mz[b] + ((size_t)mt * 128) * 4096 + p * 256 + o * 128;
    }

    float acc[4][8][4];
#pragma unroll
    for (int t = 0; t < 4; t++)
#pragma unroll
        for (int j = 0; j < 8; j++)
#pragma unroll
            for (int e = 0; e < 4; e++) acc[t][j][e] = 0.f;

    auto copyAB = [&](int g) {
        const int buf = g & 1, c0 = g * 32;
#pragma unroll
        for (int k = 0; k < 8; k++) {                // A: 1024 cp16 (hi+lo)
            int id = tid + k * 128;
            int row = id >> 3, part = id & 7, comp = part >> 2, kq = part & 3;
            cp16(sBu + buf * ABUF + row * ASTR + comp * 64 + kq * 16,
                 vsrc + (size_t)row * 512 + comp * 256 + c0 + kq * 8);
        }
#pragma unroll
        for (int k = 0; k < 4; k++) {                // B: 512 cp16
            int id = tid + k * 128;
            int row = id >> 2, part = id & 3;
            cp16(sBu + BOFF + buf * BBUF + row * BSTR + part * 16,
                 wsrc + (size_t)row * 256 + c0 + part * 8);
        }
        cp_commit();
    };

    copyAB(0);
#pragma unroll 1
    for (int g = 0; g < 8; g++) {
        const int buf = g & 1;
        cp_wait<0>();      // data for chunk g has landed
        __syncthreads();   // everyone done consuming buf (g+1)&1 from iter g-1
        if (g + 1 < 8) copyAB(g + 1);   // overlaps with compute below

        uint32_t aaddr[4], baddr[4];
#pragma unroll
        for (int t = 0; t < 4; t++) {
            int m = warp_m * 64 + t * 16 + (lid & 7) + ((lid >> 3) & 1) * 8;
            aaddr[t] = sBu + buf * ABUF + m * ASTR + ((lid >> 4) << 4);
        }
#pragma unroll
        for (int j = 0; j < 4; j++) {
            int n = warp_n * 64 + j * 16 + (lid & 7) + (lid >> 4) * 8;
            baddr[j] = sBu + BOFF + buf * BBUF + n * BSTR + (((lid >> 3) & 1) << 4);
        }

#pragma unroll
        for (int ks = 0; ks < 2; ks++) {
            uint32_t ah[4][4], al[4][4], bq[4][4];
#pragma unroll
            for (int t = 0; t < 4; t++) LDSM4(ah[t], aaddr[t] + ks * 32);
#pragma unroll
            for (int t = 0; t < 4; t++) LDSM4(al[t], aaddr[t] + ks * 32 + 64);
#pragma unroll
            for (int j = 0; j < 4; j++) LDSM4(bq[j], baddr[j] + ks * 32);
            // hi*B
#pragma unroll
            for (int t = 0; t < 4; t++)
#pragma unroll
                for (int j = 0; j < 4; j++) {
                    MMA(acc[t][2 * j],     ah[t], bq[j][0], bq[j][1]);
                    MMA(acc[t][2 * j + 1], ah[t], bq[j][2], bq[j][3]);
                }
            // lo*B
#pragma unroll
            for (int t = 0; t < 4; t++)
#pragma unroll
                for (int j = 0; j < 4; j++) {
                    MMA(acc[t][2 * j],     al[t], bq[j][0], bq[j][1]);
                    MMA(acc[t][2 * j + 1], al[t], bq[j][2], bq[j][3]);
                }
        }
    }

    // epilogue: [tile][pos][oc] stores; tile stride 4096 floats
#pragma unroll
    for (int t = 0; t < 4; t++) {
        int r = warp_m * 64 + t * 16 + (lid >> 2);
#pragma unroll
        for (int jj = 0; jj < 8; jj++) {
            int c = warp_n * 64 + (jj >> 1) * 16 + (jj & 1) * 8 + (lid & 3) * 2;
            float* base = mdst + (size_t)r * 4096 + c;
            *(float2*)base = make_float2(acc[t][jj][0], acc[t][jj][1]);
            *(float2*)(base + (size_t)8 * 4096) = make_float2(acc[t][jj][2], acc[t][jj][3]);
        }
    }
}

// ============================ inverse transform: z ===========================
__global__ __launch_bounds__(256)
void inv_z() {
    __shared__ float sOut[256 * 36];
    const int img = blockIdx.x, b = blockIdx.y;
    const int oc = threadIdx.x;
    const float bs = g_bias[2 * b][oc];
    const float* Mb = g_Mz[b];
#pragma unroll
    for (int t = 0; t < 9; t++) {
        int ty = t / 3, tx = t - ty * 3;
        const float* mp = Mb + ((size_t)img * 9 + t) * 4096 + oc;
        float Mv[16];
#pragma unroll
        for (int pos = 0; pos < 16; pos++) Mv[pos] = mp[pos * 256];
        float t0[4], t1[4];
#pragma unroll
        for (int j = 0; j < 4; j++) {
            t0[j] = Mv[j] + Mv[4 + j] + Mv[8 + j];
            t1[j] = Mv[4 + j] - Mv[8 + j] - Mv[12 + j];
        }
        sOut[oc * 36 + (2 * ty) * 6 + 2 * tx]         = t0[0] + t0[1] + t0[2] + bs;
        sOut[oc * 36 + (2 * ty) * 6 + 2 * tx + 1]     = t0[1] - t0[2] - t0[3] + bs;
        sOut[oc * 36 + (2 * ty + 1) * 6 + 2 * tx]     = t1[0] + t1[1] + t1[2] + bs;
        sOut[oc * 36 + (2 * ty + 1) * 6 + 2 * tx + 1] = t1[1] - t1[2] - t1[3] + bs;
    }
    __syncthreads();
    float* dst = g_zf[b] + (size_t)img * 256 * 36;
#pragma unroll
    for (int k = 0; k < 36; k++) {
        int f = k * 256 + threadIdx.x;
        dst[f] = sOut[f];
    }
}

// ================ fused inverse transform (x) + depthwise xcorr ==============
// Block = (ocq of 16 oc, img, branch). Phase 1: rebuild 16x30x30 xf slab in
// smem straight from M (bias folded). Phase 2: xcorr against zf, write d_out.
#define SXSTR 901
#define IX_SXF_BYTES (16 * SXSTR * 4)               // 57664
#define IX_SMEM (IX_SXF_BYTES + 16 * 36 * 4 + 64)   // 60032

__global__ __launch_bounds__(256)
void inv_xcorr(float* __restrict__ out) {
    extern __shared__ __align__(16) char ism[];
    float* sxf = (float*)ism;                        // [16][SXSTR]
    float* sz  = (float*)(ism + IX_SXF_BYTES);       // [16][36]
    float* sB  = (float*)(ism + IX_SXF_BYTES + 16 * 36 * 4);

    const int ocq = blockIdx.x, img = blockIdx.y, b = blockIdx.z;
    const int tid = threadIdx.x;
    const int ocb = ocq * 16;

    if (tid < 16) sB[tid] = g_bias[1 + 2 * b][ocb + tid];
    // zf slab: 16 oc x 36
#pragma unroll
    for (int k = 0; k < 3; k++) {
        int id = k * 256 + tid;
        if (id < 576) {
            int oc = id / 36, q = id - oc * 36;
            sz[oc * 36 + q] = g_zf[b][((size_t)img * 256 + ocb + oc) * 36 + q];
        }
    }
    __syncthreads();

    // Phase 1: 225 tiles x 16 oc = 3600 items
    const float* Mb = g_M[b] + (size_t)img * 225 * 4096 + ocb;
#pragma unroll
    for (int k = 0; k < 15; k++) {
        int it = k * 256 + tid;
        if (it < 3600) {
            int oc = it & 15, tile = it >> 4;
            int ty = tile / 15, tx = tile - ty * 15;
            const float* mp = Mb + (size_t)tile * 4096 + oc;
            float Mv[16];
#pragma unroll
            for (int pos = 0; pos < 16; pos++) Mv[pos] = mp[pos * 256];
            float t0[4], t1[4];
#pragma unroll
            for (int j = 0; j < 4; j++) {
                t0[j] = Mv[j] + Mv[4 + j] + Mv[8 + j];
                t1[j] = Mv[4 + j] - Mv[8 + j] - Mv[12 + j];
            }
            float bs = sB[oc];
            float* so = sxf + oc * SXSTR + (2 * ty) * 30 + 2 * tx;
            so[0]  = t0[0] + t0[1] + t0[2] + bs;
            so[1]  = t0[1] - t0[2] - t0[3] + bs;
            so[30] = t1[0] + t1[1] + t1[2] + bs;
            so[31] = t1[1] - t1[2] - t1[3] + bs;
        }
    }
    __syncthreads();

    // Phase 2: 16 oc x 625 outputs
    float* ob = out + (size_t)b * OSZ + ((size_t)img * 256 + ocb) * 625;
#pragma unroll 4
    for (int k = 0; k < 40; k++) {
        int it = k * 256 + tid;
        if (it < 10000) {
            int oc = it / 625, pix = it - oc * 625;
            int oy = pix / 25, ox = pix - oy * 25;
            const float* xp = sxf + oc * SXSTR + oy * 30 + ox;
            const float* zp = sz + oc * 36;
            float s = 0.f;
#pragma unroll
            for (int u = 0; u < 6; u++)
#pragma unroll
                for (int v = 0; v < 6; v++)
                    s = fmaf(zp[u * 6 + v], xp[u * 30 + v], s);
            ob[(size_t)oc * 625 + pix] = s;
        }
    }
}

// ============================ launch =========================================
extern "C" void kernel_launch(void* const* d_in, const int* in_sizes, int n_in,
                              void* d_out, int out_size) {
    const float* z = (const float*)d_in[0];
    const float* x = (const float*)d_in[1];

    PrepArgs pa;
    for (int p = 0; p < 4; p++) {
        pa.w[p] = (const float*)d_in[2 + p * 5 + 0];
        pa.g[p] = (const float*)d_in[2 + p * 5 + 1];
        pa.b[p] = (const float*)d_in[2 + p * 5 + 2];
        pa.m[p] = (const float*)d_in[2 + p * 5 + 3];
        pa.v[p] = (const float*)d_in[2 + p * 5 + 4];
    }

    cudaFuncSetAttribute(wino_gemm,
                         cudaFuncAttributeMaxDynamicSharedMemorySize, GEMM_SMEM);
    cudaFuncSetAttribute(wino_gemm,
                         cudaFuncAttributePreferredSharedMemoryCarveout, 100);
    cudaFuncSetAttribute(xform_x,
                         cudaFuncAttributeMaxDynamicSharedMemorySize, XF_SMEM);
    cudaFuncSetAttribute(inv_xcorr,
                         cudaFuncAttributeMaxDynamicSharedMemorySize, IX_SMEM);

    prep_kernel<<<1024, 256>>>(pa);
    xform_x<<<dim3(32, 4, 15), 256, XF_SMEM>>>(x);
    xform_z<<<dim3(32, 32), 128>>>(z);
    wino_gemm<<<3840, 128, GEMM_SMEM>>>();
    inv_z<<<dim3(32, 2), 256>>>();
    inv_xcorr<<<dim3(16, 32, 2), 256, IX_SMEM>>>((float*)d_out);
}